// round 8
// baseline (speedup 1.0000x reference)
#include <cuda_runtime.h>

#define N_NODES   8192
#define T_TYPES   4
#define E_EDGES   131072
#define E_TOTAL   (T_TYPES * E_EDGES)   // 524288
#define H_HEADS   4
#define D_DIM     32
#define NEG_SLOPE 0.2f

#define GRID  592                        // 4 blocks/SM on 148 SMs (152 on GB300)
#define NTHR  (GRID * 256)               // 151552

// Lossy 4-bit counting table: 2^23 fields = 4 MiB
#define LSY_LOG   23
#define LSY_WORDS (1u << (LSY_LOG - 3))  // 2^20 u32
// Exact dup hash for cnt>=2 edges (~18K entries incl. false positives)
#define DUP_BITS  16
#define DUP_SIZE  (1u << DUP_BITS)
#define DUP_MASK  (DUP_SIZE - 1u)

// Scratch — zero-init at load; self-cleaned each call.
__device__ unsigned int g_lsy[LSY_WORDS];
__device__ unsigned int g_dkey[DUP_SIZE];
__device__ unsigned int g_dcnt[DUP_SIZE];
__device__ float4 g_acc[N_NODES * 2];     // [d0,n0,d1,n1][d2,n2,d3,n3]
__device__ float4 g_srcP[N_NODES * 2];    // exp(si*wsrc_h), exp(.2*si*wsrc_h)
__device__ float4 g_tgtP[N_NODES * 2];
__device__ float4 g_Gt [T_TYPES];
__device__ float4 g_G5t[T_TYPES];
__device__ float g_wsrc[H_HEADS];
__device__ float g_wtgt[H_HEADS];
__device__ float g_embterm[H_HEADS * T_TYPES];
__device__ float g_stotal;
__device__ unsigned int g_barA, g_barB;   // grid-barrier counters (reset in k_final)

__device__ __forceinline__ void gbar(unsigned int* ctr) {
    __syncthreads();
    if (threadIdx.x == 0) {
        asm volatile("red.release.gpu.global.add.u32 [%0], %1;"
                     :: "l"(ctr), "r"(1u) : "memory");
        unsigned int v;
        do {
            asm volatile("ld.acquire.gpu.global.u32 %0, [%1];"
                         : "=r"(v) : "l"(ctr) : "memory");
        } while (v < (unsigned)GRID);
    }
    __syncthreads();
}

// ---------------------------------------------------------------------------
// One persistent kernel: prep+count | barrier | resolve | barrier | dups+clear
// ---------------------------------------------------------------------------
__global__ void __launch_bounds__(256, 4) k_main(
        const float* __restrict__ scores,
        const float* __restrict__ emb,
        const float* __restrict__ W,
        const int*   __restrict__ ei) {
    const int tid  = threadIdx.x;
    const int bid  = blockIdx.x;
    const int gtid = bid * 256 + tid;
    __shared__ float red[256];

    // ---- phase 0a: per-node factor tables, 14 nodes per block ----
    if (tid < 14) {
        int node = bid * 14 + tid;
        if (node < N_NODES) {
            float s = __ldg(scores + node);
            float E[4], E5[4], F[4], F5[4];
            #pragma unroll
            for (int h = 0; h < H_HEADS; h++) {
                float ws = __ldg(W + h * 34);
                float wt = __ldg(W + h * 34 + 33);
                E [h] = __expf(s * ws);
                E5[h] = __expf(NEG_SLOPE * s * ws);
                F [h] = __expf(s * wt);
                F5[h] = __expf(NEG_SLOPE * s * wt);
            }
            g_srcP[2*node  ] = make_float4(E [0],E [1],E [2],E [3]);
            g_srcP[2*node+1] = make_float4(E5[0],E5[1],E5[2],E5[3]);
            g_tgtP[2*node  ] = make_float4(F [0],F [1],F [2],F [3]);
            g_tgtP[2*node+1] = make_float4(F5[0],F5[1],F5[2],F5[3]);
        }
    }
    // ---- phase 0b: block 0 scalar params + S_total ----
    if (bid == 0) {
        float ss = 0.f;
        for (int k = tid; k < N_NODES; k += 256) ss += __ldg(scores + k);
        red[tid] = ss;
        __syncthreads();
        for (int o = 128; o > 0; o >>= 1) {
            if (tid < o) red[tid] += red[tid + o];
            __syncthreads();
        }
        if (tid == 0) g_stotal = red[0];
        if (tid < H_HEADS * T_TYPES) {
            int t = tid >> 2, h = tid & 3;
            float acc = 0.f;
            #pragma unroll
            for (int d = 0; d < D_DIM; d++)
                acc += __ldg(emb + t * D_DIM + d) * __ldg(W + h * 34 + 1 + d);
            g_embterm[h * T_TYPES + t] = acc;
            ((float*)g_Gt )[t * 4 + h] = __expf(acc);
            ((float*)g_G5t)[t * 4 + h] = __expf(NEG_SLOPE * acc);
        }
        if (tid >= 64 && tid < 64 + H_HEADS) {
            int h = tid - 64;
            g_wsrc[h] = __ldg(W + h * 34);
            g_wtgt[h] = __ldg(W + h * 34 + 33);
        }
    }

    // ---- phase 1: lossy counting (edges kept in registers for phase 2) ----
    unsigned int srcA[4], tgtA[4], fA[4];
    #pragma unroll
    for (int k = 0; k < 4; k++) {
        int e = gtid + k * NTHR;
        srcA[k] = 0u; tgtA[k] = 0u; fA[k] = 0u;
        if (e < E_TOTAL) {
            int t = e >> 17, el = e & (E_EDGES - 1);
            srcA[k] = (unsigned)__ldg(ei + (t * 2    ) * E_EDGES + el);
            tgtA[k] = (unsigned)__ldg(ei + (t * 2 + 1) * E_EDGES + el);
            unsigned key = (srcA[k] << 13) | tgtA[k];
            fA[k] = (key * 0x9E3779B1u) >> 9;          // 23-bit field
        }
    }
    #pragma unroll
    for (int k = 0; k < 4; k++) {
        int e = gtid + k * NTHR;
        if (e < E_TOTAL) {
            unsigned inc = 1u << ((fA[k] & 7u) * 4u);
            asm volatile("red.global.add.u32 [%0], %1;"
                         :: "l"(&g_lsy[fA[k] >> 3]), "r"(inc) : "memory");
        }
    }

    gbar(&g_barA);

    // ---- phase 2: resolve edges ----
    unsigned int wA[4];
    #pragma unroll
    for (int k = 0; k < 4; k++) {
        int e = gtid + k * NTHR;
        if (e < E_TOTAL) wA[k] = g_lsy[fA[k] >> 3];
    }
    #pragma unroll
    for (int k = 0; k < 4; k++) {
        int e = gtid + k * NTHR;
        if (e < E_TOTAL) {
            unsigned src = srcA[k], tgt = tgtA[k];
            unsigned cnt = (wA[k] >> ((fA[k] & 7u) * 4u)) & 15u;
            int t = e >> 17;
            if (cnt == 1u) {      // exact singleton: pure FMA path
                float sj = __ldg(scores + tgt);
                float4 E  = g_srcP[2*src], E5 = g_srcP[2*src+1];
                float4 F  = g_tgtP[2*tgt], F5 = g_tgtP[2*tgt+1];
                float4 G  = g_Gt[t],       G5 = g_G5t[t];
                float p, q, ex0, ex1, ex2, ex3;
                p = E.x*F.x*G.x;  q = E5.x*F5.x*G5.x;  ex0 = (p >= 1.f ? p : q) - 1.f;
                p = E.y*F.y*G.y;  q = E5.y*F5.y*G5.y;  ex1 = (p >= 1.f ? p : q) - 1.f;
                p = E.z*F.z*G.z;  q = E5.z*F5.z*G5.z;  ex2 = (p >= 1.f ? p : q) - 1.f;
                p = E.w*F.w*G.w;  q = E5.w*F5.w*G5.w;  ex3 = (p >= 1.f ? p : q) - 1.f;
                float4* dst = &g_acc[src * 2];
                asm volatile("red.global.add.v4.f32 [%0], {%1,%2,%3,%4};"
                             :: "l"(dst), "f"(ex0), "f"(ex0 * sj),
                                "f"(ex1), "f"(ex1 * sj) : "memory");
                asm volatile("red.global.add.v4.f32 [%0], {%1,%2,%3,%4};"
                             :: "l"(dst + 1), "f"(ex2), "f"(ex2 * sj),
                                "f"(ex3), "f"(ex3 * sj) : "memory");
            } else {              // rare: register exact key + type count
                unsigned key = (src << 13) | tgt;
                unsigned hh = key * 0x85EBCA6Bu;
                hh = (hh ^ (hh >> 16)) & DUP_MASK;
                while (true) {
                    unsigned o = atomicCAS(&g_dkey[hh], 0u, key + 1u);
                    if (o == 0u || o == key + 1u) break;
                    hh = (hh + 1u) & DUP_MASK;
                }
                asm volatile("red.global.add.u32 [%0], %1;"
                             :: "l"(&g_dcnt[hh]), "r"(1u << (t * 8)) : "memory");
            }
        }
    }

    gbar(&g_barB);

    // ---- phase 3: resolve dup groups (exact, incl. m=1 false positives) ----
    if (gtid < DUP_SIZE) {
        unsigned keyp = g_dkey[gtid];
        if (keyp != 0u) {
            unsigned c = g_dcnt[gtid];
            g_dkey[gtid] = 0u;
            g_dcnt[gtid] = 0u;
            unsigned key = keyp - 1u;
            unsigned i = key >> 13, j = key & 8191u;
            float si = __ldg(scores + i);
            float sj = __ldg(scores + j);
            float c0 = (float)( c        & 0xFFu);
            float c1 = (float)((c >> 8 ) & 0xFFu);
            float c2 = (float)((c >> 16) & 0xFFu);
            float c3 = (float)((c >> 24) & 0xFFu);
            float ctot = c0 + c1 + c2 + c3;
            float ex[4];
            #pragma unroll
            for (int h = 0; h < H_HEADS; h++) {
                float a = (si * g_wsrc[h] + sj * g_wtgt[h]) * ctot
                        + c0 * g_embterm[h * T_TYPES + 0]
                        + c1 * g_embterm[h * T_TYPES + 1]
                        + c2 * g_embterm[h * T_TYPES + 2]
                        + c3 * g_embterm[h * T_TYPES + 3];
                a = (a >= 0.f) ? a : NEG_SLOPE * a;
                ex[h] = __expf(a) - 1.f;
            }
            float4* dst = &g_acc[i * 2];
            asm volatile("red.global.add.v4.f32 [%0], {%1,%2,%3,%4};"
                         :: "l"(dst), "f"(ex[0]), "f"(ex[0] * sj),
                            "f"(ex[1]), "f"(ex[1] * sj) : "memory");
            asm volatile("red.global.add.v4.f32 [%0], {%1,%2,%3,%4};"
                         :: "l"(dst + 1), "f"(ex[2]), "f"(ex[2] * sj),
                            "f"(ex[3]), "f"(ex[3] * sj) : "memory");
        }
    }
    // clear lossy table (4 MiB, coalesced uint4)
    {
        uint4* l4 = (uint4*)g_lsy;
        uint4 z4 = make_uint4(0u, 0u, 0u, 0u);
        #pragma unroll
        for (int k = 0; k < 2; k++) {
            unsigned u = (unsigned)gtid + k * NTHR;
            if (u < (LSY_WORDS >> 2)) l4[u] = z4;
        }
    }
}

// ---------------------------------------------------------------------------
// k_final: finalize outputs, reset g_acc + barrier counters.
// ---------------------------------------------------------------------------
__global__ void __launch_bounds__(256) k_final(float* __restrict__ out) {
    int i = blockIdx.x * 256 + threadIdx.x;
    float st = g_stotal;
    float4 a0 = g_acc[i * 2];
    float4 a1 = g_acc[i * 2 + 1];
    out[i] = 0.25f * ((st + a0.y) / (8192.f + a0.x)
                    + (st + a0.w) / (8192.f + a0.z)
                    + (st + a1.y) / (8192.f + a1.x)
                    + (st + a1.w) / (8192.f + a1.z));
    g_acc[i * 2]     = make_float4(0.f, 0.f, 0.f, 0.f);
    g_acc[i * 2 + 1] = make_float4(0.f, 0.f, 0.f, 0.f);
    if (i == 0) { g_barA = 0u; g_barB = 0u; }
}

// ---------------------------------------------------------------------------
extern "C" void kernel_launch(void* const* d_in, const int* in_sizes, int n_in,
                              void* d_out, int out_size) {
    const float* scores = (const float*)d_in[0];   // (N, 1)
    const float* emb    = (const float*)d_in[1];   // (T, D)
    const int*   ei     = (const int*)  d_in[2];   // (T, 2, E)
    const float* W      = (const float*)d_in[3];   // (H, D+2, 1)
    float*       out    = (float*)d_out;           // (N, 1)

    k_main <<<GRID, 256>>>(scores, emb, W, ei);
    k_final<<<N_NODES / 256, 256>>>(out);
}

// round 9
// speedup vs baseline: 1.2684x; 1.2684x over previous
#include <cuda_runtime.h>

#define N_NODES   8192
#define T_TYPES   4
#define E_EDGES   131072
#define E_TOTAL   (T_TYPES * E_EDGES)   // 524288
#define H_HEADS   4
#define D_DIM     32
#define NEG_SLOPE 0.2f
#define WSTR      34                    // D_DIM + 2

// Lossy 4-bit counting table: 2^23 fields packed 8/word = 4 MiB
#define LSY_WORDS (1u << 20)
// Exact dup hash (true dups + field-collision false positives, ~35K keys)
#define DUP_BITS  17
#define DUP_SIZE  (1u << DUP_BITS)
#define DUP_MASK  (DUP_SIZE - 1u)

#define K12_BLOCKS  (E_TOTAL / 512)     // 1024 (2 edges/thread)
#define SCAN_BLOCKS 512                 // DUP_SIZE / 256
#define CLR_BLOCKS  64
#define FIN_BLOCKS  (N_NODES / 256)     // 32
#define K3_BLOCKS   (SCAN_BLOCKS + CLR_BLOCKS + FIN_BLOCKS)  // 608

// Scratch — zero-init at module load; self-cleaned every call.
__device__ unsigned int g_lsy[LSY_WORDS];
__device__ unsigned int g_dkey[DUP_SIZE];   // 0=empty else key+1
__device__ unsigned int g_dcnt[DUP_SIZE];   // packed per-type byte counts
__device__ float4 g_acc[N_NODES * 2];       // [d0,n0,d1,n1][d2,n2,d3,n3]
__device__ float4 g_embT[T_TYPES];          // embterm[t] over 4 heads
__device__ float  g_part[32];               // score partial sums
__device__ unsigned int g_done;             // K3 scan-done counter

__device__ __forceinline__ unsigned int field_of(unsigned int key) {
    return (key * 0x9E3779B1u) >> 9;        // 23-bit field index
}

// ---------------------------------------------------------------------------
// K1: lossy counting (fire-and-forget REDG, no return dependence) +
//     distributed score partials + embterm. Resets g_done.
// ---------------------------------------------------------------------------
__global__ void __launch_bounds__(256) k_count(
        const int*   __restrict__ ei,
        const float* __restrict__ scores,
        const float* __restrict__ emb,
        const float* __restrict__ W) {
    const int bid = blockIdx.x, tid = threadIdx.x;
    const int gtid = bid * 256 + tid;
    const int base = gtid * 2;
    const int t = base >> 17, e = base & (E_EDGES - 1);
    int2 s2 = __ldg((const int2*)(ei + (t * 2    ) * E_EDGES + e));
    int2 t2 = __ldg((const int2*)(ei + (t * 2 + 1) * E_EDGES + e));

    unsigned int k0 = ((unsigned)s2.x << 13) | (unsigned)t2.x;
    unsigned int k1 = ((unsigned)s2.y << 13) | (unsigned)t2.y;
    unsigned int f0 = field_of(k0), f1 = field_of(k1);
    asm volatile("red.global.add.u32 [%0], %1;"
                 :: "l"(&g_lsy[f0 >> 3]), "r"(1u << ((f0 & 7u) * 4u)) : "memory");
    asm volatile("red.global.add.u32 [%0], %1;"
                 :: "l"(&g_lsy[f1 >> 3]), "r"(1u << ((f1 & 7u) * 4u)) : "memory");

    if (bid < 32) {                    // deterministic per-block score partials
        __shared__ float red[256];
        red[tid] = __ldg(scores + bid * 256 + tid);
        __syncthreads();
        for (int o = 128; o > 0; o >>= 1) {
            if (tid < o) red[tid] += red[tid + o];
            __syncthreads();
        }
        if (tid == 0) g_part[bid] = red[0];
    } else if (bid == 32) {
        if (tid < T_TYPES) {           // embterm[t] over heads
            float r[H_HEADS];
            #pragma unroll
            for (int h = 0; h < H_HEADS; h++) {
                float a = 0.f;
                #pragma unroll
                for (int d = 0; d < D_DIM; d++)
                    a += __ldg(emb + tid * D_DIM + d) * __ldg(W + h * WSTR + 1 + d);
                r[h] = a;
            }
            g_embT[tid] = make_float4(r[0], r[1], r[2], r[3]);
        }
        if (tid == 255) g_done = 0u;   // reset for this call's K3
    }
}

// ---------------------------------------------------------------------------
// K2: resolve edges directly (no factor tables). Field count==1 → compute
// a_h = si*wsrc + sj*wtgt + emb[h][t], leaky, __expf, REDG.v4 ×2.
// count>=2 → register exact key + packed type count in dup hash.
// ---------------------------------------------------------------------------
__device__ __forceinline__ void resolve_edge(
        const float* __restrict__ scores,
        unsigned int src, unsigned int tgt, int t,
        float4 embT,
        float ws0, float ws1, float ws2, float ws3,
        float wt0, float wt1, float wt2, float wt3) {
    unsigned int key = (src << 13) | tgt;
    unsigned int f = field_of(key);
    unsigned int w = __ldg(&g_lsy[f >> 3]);
    unsigned int cnt = (w >> ((f & 7u) * 4u)) & 15u;

    if (cnt == 1u) {
        float si = __ldg(scores + src);
        float sj = __ldg(scores + tgt);
        float a0 = si * ws0 + sj * wt0 + embT.x;
        float a1 = si * ws1 + sj * wt1 + embT.y;
        float a2 = si * ws2 + sj * wt2 + embT.z;
        float a3 = si * ws3 + sj * wt3 + embT.w;
        float ex0 = __expf(fmaxf(a0, NEG_SLOPE * a0)) - 1.f;
        float ex1 = __expf(fmaxf(a1, NEG_SLOPE * a1)) - 1.f;
        float ex2 = __expf(fmaxf(a2, NEG_SLOPE * a2)) - 1.f;
        float ex3 = __expf(fmaxf(a3, NEG_SLOPE * a3)) - 1.f;
        float4* dst = &g_acc[src * 2];
        asm volatile("red.global.add.v4.f32 [%0], {%1,%2,%3,%4};"
                     :: "l"(dst), "f"(ex0), "f"(ex0 * sj),
                        "f"(ex1), "f"(ex1 * sj) : "memory");
        asm volatile("red.global.add.v4.f32 [%0], {%1,%2,%3,%4};"
                     :: "l"(dst + 1), "f"(ex2), "f"(ex2 * sj),
                        "f"(ex3), "f"(ex3 * sj) : "memory");
    } else {    // ~6% of edges (true dups + field collisions): exact hash
        unsigned int hh = key * 0x85EBCA6Bu;
        hh = (hh ^ (hh >> 16)) & DUP_MASK;
        while (true) {
            unsigned int o = atomicCAS(&g_dkey[hh], 0u, key + 1u);
            if (o == 0u || o == key + 1u) break;
            hh = (hh + 1u) & DUP_MASK;
        }
        asm volatile("red.global.add.u32 [%0], %1;"
                     :: "l"(&g_dcnt[hh]), "r"(1u << (t * 8)) : "memory");
    }
}

__global__ void __launch_bounds__(256) k_edges(
        const int*   __restrict__ ei,
        const float* __restrict__ scores,
        const float* __restrict__ W) {
    const int gtid = blockIdx.x * 256 + threadIdx.x;
    const int base = gtid * 2;
    const int t = base >> 17, e = base & (E_EDGES - 1);
    int2 s2 = __ldg((const int2*)(ei + (t * 2    ) * E_EDGES + e));
    int2 t2 = __ldg((const int2*)(ei + (t * 2 + 1) * E_EDGES + e));

    float4 embT = g_embT[t];
    float ws0 = __ldg(W + 0 * WSTR), wt0 = __ldg(W + 0 * WSTR + 33);
    float ws1 = __ldg(W + 1 * WSTR), wt1 = __ldg(W + 1 * WSTR + 33);
    float ws2 = __ldg(W + 2 * WSTR), wt2 = __ldg(W + 2 * WSTR + 33);
    float ws3 = __ldg(W + 3 * WSTR), wt3 = __ldg(W + 3 * WSTR + 33);

    resolve_edge(scores, (unsigned)s2.x, (unsigned)t2.x, t, embT,
                 ws0, ws1, ws2, ws3, wt0, wt1, wt2, wt3);
    resolve_edge(scores, (unsigned)s2.y, (unsigned)t2.y, t, embT,
                 ws0, ws1, ws2, ws3, wt0, wt1, wt2, wt3);
}

// ---------------------------------------------------------------------------
// K3: blocks [0,512) scan+resolve dup hash (self-clean) then signal g_done;
//     blocks [512,576) clear the 4 MiB lossy table;
//     blocks [576,608) wait for g_done==512, finalize outputs, reset g_acc.
// Deadlock-free: waiters depend only on non-waiting blocks; 608 blocks all
// co-resident (256 thr, low regs → ≥6 blocks/SM × 148 SMs > 608).
// ---------------------------------------------------------------------------
__global__ void __launch_bounds__(256) k_final(
        float* __restrict__ out,
        const float* __restrict__ scores,
        const float* __restrict__ W) {
    const int bid = blockIdx.x, tid = threadIdx.x;

    if (bid < SCAN_BLOCKS) {
        unsigned int slot = bid * 256 + tid;
        unsigned int keyp = g_dkey[slot];
        if (keyp != 0u) {
            unsigned int c = g_dcnt[slot];
            g_dkey[slot] = 0u;
            g_dcnt[slot] = 0u;
            unsigned int key = keyp - 1u;
            unsigned int i = key >> 13, j = key & 8191u;
            float si = __ldg(scores + i);
            float sj = __ldg(scores + j);
            float c0 = (float)( c        & 0xFFu);
            float c1 = (float)((c >> 8 ) & 0xFFu);
            float c2 = (float)((c >> 16) & 0xFFu);
            float c3 = (float)((c >> 24) & 0xFFu);
            float ctot = c0 + c1 + c2 + c3;
            float4 e0 = g_embT[0], e1 = g_embT[1], e2 = g_embT[2], e3 = g_embT[3];
            float ex[H_HEADS];
            #pragma unroll
            for (int h = 0; h < H_HEADS; h++) {
                float ws = __ldg(W + h * WSTR);
                float wt = __ldg(W + h * WSTR + 33);
                float eh = (h == 0) ? (c0*e0.x + c1*e1.x + c2*e2.x + c3*e3.x)
                         : (h == 1) ? (c0*e0.y + c1*e1.y + c2*e2.y + c3*e3.y)
                         : (h == 2) ? (c0*e0.z + c1*e1.z + c2*e2.z + c3*e3.z)
                                    : (c0*e0.w + c1*e1.w + c2*e2.w + c3*e3.w);
                float a = (si * ws + sj * wt) * ctot + eh;
                ex[h] = __expf(fmaxf(a, NEG_SLOPE * a)) - 1.f;
            }
            float4* dst = &g_acc[i * 2];
            asm volatile("red.global.add.v4.f32 [%0], {%1,%2,%3,%4};"
                         :: "l"(dst), "f"(ex[0]), "f"(ex[0] * sj),
                            "f"(ex[1]), "f"(ex[1] * sj) : "memory");
            asm volatile("red.global.add.v4.f32 [%0], {%1,%2,%3,%4};"
                         :: "l"(dst + 1), "f"(ex[2]), "f"(ex[2] * sj),
                            "f"(ex[3]), "f"(ex[3] * sj) : "memory");
        }
        __syncthreads();
        if (tid == 0)
            asm volatile("red.release.gpu.global.add.u32 [%0], %1;"
                         :: "l"(&g_done), "r"(1u) : "memory");
    } else if (bid < SCAN_BLOCKS + CLR_BLOCKS) {
        // clear lossy table: 2^18 uint4 over 64 blocks × 256 threads × 16 iters
        uint4* l4 = (uint4*)g_lsy;
        uint4 z4 = make_uint4(0u, 0u, 0u, 0u);
        unsigned int b = (unsigned)(bid - SCAN_BLOCKS) * 256 + tid;
        #pragma unroll
        for (int k = 0; k < 16; k++)
            l4[b + k * (CLR_BLOCKS * 256)] = z4;
    } else {
        if (tid == 0) {
            unsigned int v;
            do {
                asm volatile("ld.acquire.gpu.global.u32 %0, [%1];"
                             : "=r"(v) : "l"(&g_done) : "memory");
            } while (v < (unsigned)SCAN_BLOCKS);
        }
        __syncthreads();

        float st = 0.f;
        #pragma unroll
        for (int k = 0; k < 32; k++) st += g_part[k];   // deterministic order

        int i = (bid - SCAN_BLOCKS - CLR_BLOCKS) * 256 + tid;
        float4 a0 = g_acc[i * 2];
        float4 a1 = g_acc[i * 2 + 1];
        out[i] = 0.25f * ((st + a0.y) / (8192.f + a0.x)
                        + (st + a0.w) / (8192.f + a0.z)
                        + (st + a1.y) / (8192.f + a1.x)
                        + (st + a1.w) / (8192.f + a1.z));
        g_acc[i * 2]     = make_float4(0.f, 0.f, 0.f, 0.f);
        g_acc[i * 2 + 1] = make_float4(0.f, 0.f, 0.f, 0.f);
    }
}

// ---------------------------------------------------------------------------
extern "C" void kernel_launch(void* const* d_in, const int* in_sizes, int n_in,
                              void* d_out, int out_size) {
    const float* scores = (const float*)d_in[0];   // (N, 1)
    const float* emb    = (const float*)d_in[1];   // (T, D)
    const int*   ei     = (const int*)  d_in[2];   // (T, 2, E)
    const float* W      = (const float*)d_in[3];   // (H, D+2, 1)
    float*       out    = (float*)d_out;           // (N, 1)

    k_count<<<K12_BLOCKS, 256>>>(ei, scores, emb, W);
    k_edges<<<K12_BLOCKS, 256>>>(ei, scores, W);
    k_final<<<K3_BLOCKS,  256>>>(out, scores, W);
}

// round 11
// speedup vs baseline: 1.2697x; 1.0010x over previous
#include <cuda_runtime.h>

#define N_NODES   8192
#define T_TYPES   4
#define E_EDGES   131072
#define E_TOTAL   (T_TYPES * E_EDGES)   // 524288
#define H_HEADS   4
#define D_DIM     32
#define NEG_SLOPE 0.2f
#define WSTR      34                    // D_DIM + 2

// Lossy 4-bit counting table: 2^23 fields packed 8/word = 4 MiB
#define LSY_WORDS (1u << 20)
// Exact dup hash (true dups + field-collision false positives, ~35K keys)
#define DUP_BITS  17
#define DUP_SIZE  (1u << DUP_BITS)
#define DUP_MASK  (DUP_SIZE - 1u)

#define GRID1       512                 // 4 edges/thread; 512 <= 4/SM*148 → all resident
#define SCAN_BLOCKS 512                 // DUP_SIZE / 256
#define CLR_BLOCKS  64
#define FIN_BLOCKS  (N_NODES / 256)     // 32
#define K2_BLOCKS   (SCAN_BLOCKS + CLR_BLOCKS + FIN_BLOCKS)  // 608

// Scratch — zero-init at module load; self-cleaned every call.
__device__ unsigned int g_lsy[LSY_WORDS];
__device__ unsigned int g_dkey[DUP_SIZE];   // 0=empty else key+1
__device__ unsigned int g_dcnt[DUP_SIZE];   // packed per-type byte counts
__device__ float4 g_acc[N_NODES * 2];       // [d0,n0,d1,n1][d2,n2,d3,n3]
__device__ float4 g_embT[T_TYPES];          // embterm[t] over 4 heads
__device__ float  g_part[32];               // score partial sums
__device__ unsigned int g_barA;             // K1 grid barrier (reset in K2)
__device__ unsigned int g_done;             // K2 scan-done counter (reset in K1)

__device__ __forceinline__ unsigned int field_of(unsigned int key) {
    return (key * 0x9E3779B1u) >> 9;        // 23-bit field index
}

// L2-coherent load (bypasses L1 / read-only path) — REQUIRED for data
// mutated within this kernel launch. __ldg here is UB and was the R10 bug.
__device__ __forceinline__ unsigned int ld_cg_u32(const unsigned int* p) {
    unsigned int v;
    asm volatile("ld.global.cg.u32 %0, [%1];" : "=r"(v) : "l"(p) : "memory");
    return v;
}
__device__ __forceinline__ float4 ld_cg_f4(const float4* p) {
    float4 v;
    asm volatile("ld.global.cg.v4.f32 {%0,%1,%2,%3}, [%4];"
                 : "=f"(v.x), "=f"(v.y), "=f"(v.z), "=f"(v.w) : "l"(p) : "memory");
    return v;
}

// ---------------------------------------------------------------------------
// K1: [count + prep] -> threadfence -> grid barrier (all blocks resident)
//     -> [resolve].  Edges stay in registers across the barrier.
// ---------------------------------------------------------------------------
__global__ void __launch_bounds__(256, 4) k_main(
        const int*   __restrict__ ei,
        const float* __restrict__ scores,
        const float* __restrict__ emb,
        const float* __restrict__ W) {
    const int bid = blockIdx.x, tid = threadIdx.x;
    const int gtid = bid * 256 + tid;
    const int base = gtid * 4;              // 4 contiguous edges, same type t
    const int t = base >> 17, e = base & (E_EDGES - 1);

    int4 s4 = __ldg((const int4*)(ei + (t * 2    ) * E_EDGES + e));
    int4 t4 = __ldg((const int4*)(ei + (t * 2 + 1) * E_EDGES + e));

    unsigned int key[4], f[4];
    key[0] = ((unsigned)s4.x << 13) | (unsigned)t4.x;  f[0] = field_of(key[0]);
    key[1] = ((unsigned)s4.y << 13) | (unsigned)t4.y;  f[1] = field_of(key[1]);
    key[2] = ((unsigned)s4.z << 13) | (unsigned)t4.z;  f[2] = field_of(key[2]);
    key[3] = ((unsigned)s4.w << 13) | (unsigned)t4.w;  f[3] = field_of(key[3]);

    #pragma unroll
    for (int k = 0; k < 4; k++)
        asm volatile("red.global.add.u32 [%0], %1;"
                     :: "l"(&g_lsy[f[k] >> 3]),
                        "r"(1u << ((f[k] & 7u) * 4u)) : "memory");

    // distributed prep, overlapped with count drain
    if (bid < 32) {
        __shared__ float red[256];
        red[tid] = __ldg(scores + bid * 256 + tid);
        __syncthreads();
        for (int o = 128; o > 0; o >>= 1) {
            if (tid < o) red[tid] += red[tid + o];
            __syncthreads();
        }
        if (tid == 0) g_part[bid] = red[0];
    } else if (bid == 32) {
        if (tid < T_TYPES) {
            float r[H_HEADS];
            #pragma unroll
            for (int h = 0; h < H_HEADS; h++) {
                float a = 0.f;
                #pragma unroll
                for (int d = 0; d < D_DIM; d++)
                    a += __ldg(emb + tid * D_DIM + d) * __ldg(W + h * WSTR + 1 + d);
                r[h] = a;
            }
            g_embT[tid] = make_float4(r[0], r[1], r[2], r[3]);
        }
        if (tid == 255) g_done = 0u;        // reset for this call's K2
    }

    // make this thread's REDs GPU-visible before the barrier arrive
    __threadfence();

    // ---- grid barrier: all 512 blocks co-resident → deadlock-free ----
    __syncthreads();
    if (tid == 0) {
        asm volatile("red.release.gpu.global.add.u32 [%0], %1;"
                     :: "l"(&g_barA), "r"(1u) : "memory");
        unsigned int v;
        do {
            asm volatile("ld.acquire.gpu.global.u32 %0, [%1];"
                         : "=r"(v) : "l"(&g_barA) : "memory");
        } while (v < (unsigned)GRID1);
    }
    __syncthreads();

    // ---- resolve (edges still in registers); coherent .cg reads ----
    unsigned int w[4];
    #pragma unroll
    for (int k = 0; k < 4; k++) w[k] = ld_cg_u32(&g_lsy[f[k] >> 3]);

    float4 embT = ld_cg_f4(&g_embT[t]);
    float ws0 = __ldg(W + 0 * WSTR), wt0 = __ldg(W + 0 * WSTR + 33);
    float ws1 = __ldg(W + 1 * WSTR), wt1 = __ldg(W + 1 * WSTR + 33);
    float ws2 = __ldg(W + 2 * WSTR), wt2 = __ldg(W + 2 * WSTR + 33);
    float ws3 = __ldg(W + 3 * WSTR), wt3 = __ldg(W + 3 * WSTR + 33);

    #pragma unroll
    for (int k = 0; k < 4; k++) {
        unsigned int cnt = (w[k] >> ((f[k] & 7u) * 4u)) & 15u;
        unsigned int src = key[k] >> 13, tgt = key[k] & 8191u;
        if (cnt == 1u) {                    // exact singleton
            float si = __ldg(scores + src);
            float sj = __ldg(scores + tgt);
            float a0 = si * ws0 + sj * wt0 + embT.x;
            float a1 = si * ws1 + sj * wt1 + embT.y;
            float a2 = si * ws2 + sj * wt2 + embT.z;
            float a3 = si * ws3 + sj * wt3 + embT.w;
            float ex0 = __expf(fmaxf(a0, NEG_SLOPE * a0)) - 1.f;
            float ex1 = __expf(fmaxf(a1, NEG_SLOPE * a1)) - 1.f;
            float ex2 = __expf(fmaxf(a2, NEG_SLOPE * a2)) - 1.f;
            float ex3 = __expf(fmaxf(a3, NEG_SLOPE * a3)) - 1.f;
            float4* dst = &g_acc[src * 2];
            asm volatile("red.global.add.v4.f32 [%0], {%1,%2,%3,%4};"
                         :: "l"(dst), "f"(ex0), "f"(ex0 * sj),
                            "f"(ex1), "f"(ex1 * sj) : "memory");
            asm volatile("red.global.add.v4.f32 [%0], {%1,%2,%3,%4};"
                         :: "l"(dst + 1), "f"(ex2), "f"(ex2 * sj),
                            "f"(ex3), "f"(ex3 * sj) : "memory");
        } else {                            // dup or collision: exact hash
            unsigned int hh = key[k] * 0x85EBCA6Bu;
            hh = (hh ^ (hh >> 16)) & DUP_MASK;
            while (true) {
                unsigned int o = atomicCAS(&g_dkey[hh], 0u, key[k] + 1u);
                if (o == 0u || o == key[k] + 1u) break;
                hh = (hh + 1u) & DUP_MASK;
            }
            asm volatile("red.global.add.u32 [%0], %1;"
                         :: "l"(&g_dcnt[hh]), "r"(1u << (t * 8)) : "memory");
        }
    }
}

// ---------------------------------------------------------------------------
// K2: blocks [0,512) scan+resolve dup hash (self-clean) then signal g_done;
//     blocks [512,576) clear lossy table (+ reset g_barA);
//     blocks [576,608) wait g_done==512, finalize outputs, reset g_acc.
// ---------------------------------------------------------------------------
__global__ void __launch_bounds__(256) k_final(
        float* __restrict__ out,
        const float* __restrict__ scores,
        const float* __restrict__ W) {
    const int bid = blockIdx.x, tid = threadIdx.x;

    if (bid < SCAN_BLOCKS) {
        unsigned int slot = bid * 256 + tid;
        unsigned int keyp = g_dkey[slot];
        if (keyp != 0u) {
            unsigned int c = g_dcnt[slot];
            g_dkey[slot] = 0u;
            g_dcnt[slot] = 0u;
            unsigned int key = keyp - 1u;
            unsigned int i = key >> 13, j = key & 8191u;
            float si = __ldg(scores + i);
            float sj = __ldg(scores + j);
            float c0 = (float)( c        & 0xFFu);
            float c1 = (float)((c >> 8 ) & 0xFFu);
            float c2 = (float)((c >> 16) & 0xFFu);
            float c3 = (float)((c >> 24) & 0xFFu);
            float ctot = c0 + c1 + c2 + c3;
            float4 e0 = g_embT[0], e1 = g_embT[1], e2 = g_embT[2], e3 = g_embT[3];
            float ex[H_HEADS];
            #pragma unroll
            for (int h = 0; h < H_HEADS; h++) {
                float ws = __ldg(W + h * WSTR);
                float wt = __ldg(W + h * WSTR + 33);
                float eh = (h == 0) ? (c0*e0.x + c1*e1.x + c2*e2.x + c3*e3.x)
                         : (h == 1) ? (c0*e0.y + c1*e1.y + c2*e2.y + c3*e3.y)
                         : (h == 2) ? (c0*e0.z + c1*e1.z + c2*e2.z + c3*e3.z)
                                    : (c0*e0.w + c1*e1.w + c2*e2.w + c3*e3.w);
                float a = (si * ws + sj * wt) * ctot + eh;
                ex[h] = __expf(fmaxf(a, NEG_SLOPE * a)) - 1.f;
            }
            float4* dst = &g_acc[i * 2];
            asm volatile("red.global.add.v4.f32 [%0], {%1,%2,%3,%4};"
                         :: "l"(dst), "f"(ex[0]), "f"(ex[0] * sj),
                            "f"(ex[1]), "f"(ex[1] * sj) : "memory");
            asm volatile("red.global.add.v4.f32 [%0], {%1,%2,%3,%4};"
                         :: "l"(dst + 1), "f"(ex[2]), "f"(ex[2] * sj),
                            "f"(ex[3]), "f"(ex[3] * sj) : "memory");
        }
        __threadfence();
        __syncthreads();
        if (tid == 0)
            asm volatile("red.release.gpu.global.add.u32 [%0], %1;"
                         :: "l"(&g_done), "r"(1u) : "memory");
    } else if (bid < SCAN_BLOCKS + CLR_BLOCKS) {
        if (bid == SCAN_BLOCKS && tid == 0) g_barA = 0u;   // reset K1 barrier
        uint4* l4 = (uint4*)g_lsy;
        uint4 z4 = make_uint4(0u, 0u, 0u, 0u);
        unsigned int b = (unsigned)(bid - SCAN_BLOCKS) * 256 + tid;
        #pragma unroll
        for (int k = 0; k < 16; k++)
            l4[b + k * (CLR_BLOCKS * 256)] = z4;
    } else {
        if (tid == 0) {
            unsigned int v;
            do {
                asm volatile("ld.acquire.gpu.global.u32 %0, [%1];"
                             : "=r"(v) : "l"(&g_done) : "memory");
            } while (v < (unsigned)SCAN_BLOCKS);
        }
        __syncthreads();

        float st = 0.f;
        #pragma unroll
        for (int k = 0; k < 32; k++) st += g_part[k];   // deterministic order

        int i = (bid - SCAN_BLOCKS - CLR_BLOCKS) * 256 + tid;
        float4 a0 = ld_cg_f4(&g_acc[i * 2]);
        float4 a1 = ld_cg_f4(&g_acc[i * 2 + 1]);
        out[i] = 0.25f * ((st + a0.y) / (8192.f + a0.x)
                        + (st + a0.w) / (8192.f + a0.z)
                        + (st + a1.y) / (8192.f + a1.x)
                        + (st + a1.w) / (8192.f + a1.z));
        g_acc[i * 2]     = make_float4(0.f, 0.f, 0.f, 0.f);
        g_acc[i * 2 + 1] = make_float4(0.f, 0.f, 0.f, 0.f);
    }
}

// ---------------------------------------------------------------------------
extern "C" void kernel_launch(void* const* d_in, const int* in_sizes, int n_in,
                              void* d_out, int out_size) {
    const float* scores = (const float*)d_in[0];   // (N, 1)
    const float* emb    = (const float*)d_in[1];   // (T, D)
    const int*   ei     = (const int*)  d_in[2];   // (T, 2, E)
    const float* W      = (const float*)d_in[3];   // (H, D+2, 1)
    float*       out    = (float*)d_out;           // (N, 1)

    k_main <<<GRID1,     256>>>(ei, scores, emb, W);
    k_final<<<K2_BLOCKS, 256>>>(out, scores, W);
}

// round 12
// speedup vs baseline: 1.4809x; 1.1663x over previous
#include <cuda_runtime.h>

#define N_NODES   8192
#define T_TYPES   4
#define E_EDGES   131072
#define E_TOTAL   (T_TYPES * E_EDGES)   // 524288
#define H_HEADS   4
#define D_DIM     32
#define NEG_SLOPE 0.2f
#define WSTR      34                    // D_DIM + 2

// Lossy 4-bit counting table: 2^23 fields packed 8/word = 4 MiB
#define LSY_WORDS (1u << 20)
// Exact dup hash (true dups + ~6% lossy false positives, ~32K keys)
#define DUP_BITS  17
#define DUP_SIZE  (1u << DUP_BITS)
#define DUP_MASK  (DUP_SIZE - 1u)

#define EDGE_BLOCKS 512                 // 4 edges/thread
#define FIN_BLOCKS  32                  // 8192/256
#define CLR_L_BLOCKS 64
#define CLR_D_BLOCKS 32
#define K3_BLOCKS   (FIN_BLOCKS + CLR_L_BLOCKS + CLR_D_BLOCKS)  // 128

// Scratch — zero-init at module load; self-cleaned every call (K3).
__device__ unsigned int g_lsy[LSY_WORDS];
__device__ unsigned int g_dkey[DUP_SIZE];   // 0=empty else key+1
__device__ unsigned int g_dcnt[DUP_SIZE];   // packed per-type byte counts
__device__ float4 g_acc[N_NODES * 2];       // [d0,n0,d1,n1][d2,n2,d3,n3]
__device__ float4 g_embT[T_TYPES];          // embterm[t] over 4 heads
__device__ float  g_part[32];               // score partial sums

__device__ __forceinline__ unsigned int field_of(unsigned int key) {
    return (key * 0x9E3779B1u) >> 9;        // 23-bit field index
}

// ---------------------------------------------------------------------------
// K1: lossy counting (fire-and-forget REDs) + distributed prep. No sync.
// ---------------------------------------------------------------------------
__global__ void __launch_bounds__(256) k_count(
        const int*   __restrict__ ei,
        const float* __restrict__ scores,
        const float* __restrict__ emb,
        const float* __restrict__ W) {
    const int bid = blockIdx.x, tid = threadIdx.x;
    const int gtid = bid * 256 + tid;
    const int base = gtid * 4;              // 4 contiguous edges, same type t
    const int t = base >> 17, e = base & (E_EDGES - 1);

    int4 s4 = __ldg((const int4*)(ei + (t * 2    ) * E_EDGES + e));
    int4 t4 = __ldg((const int4*)(ei + (t * 2 + 1) * E_EDGES + e));

    unsigned int f[4];
    f[0] = field_of(((unsigned)s4.x << 13) | (unsigned)t4.x);
    f[1] = field_of(((unsigned)s4.y << 13) | (unsigned)t4.y);
    f[2] = field_of(((unsigned)s4.z << 13) | (unsigned)t4.z);
    f[3] = field_of(((unsigned)s4.w << 13) | (unsigned)t4.w);

    #pragma unroll
    for (int k = 0; k < 4; k++)
        asm volatile("red.global.add.u32 [%0], %1;"
                     :: "l"(&g_lsy[f[k] >> 3]),
                        "r"(1u << ((f[k] & 7u) * 4u)) : "memory");

    if (bid < 32) {                         // per-block score partials
        __shared__ float red[256];
        red[tid] = __ldg(scores + bid * 256 + tid);
        __syncthreads();
        for (int o = 128; o > 0; o >>= 1) {
            if (tid < o) red[tid] += red[tid + o];
            __syncthreads();
        }
        if (tid == 0) g_part[bid] = red[0];
    } else if (bid == 32 && tid < T_TYPES) {
        float r[H_HEADS];
        #pragma unroll
        for (int h = 0; h < H_HEADS; h++) {
            float a = 0.f;
            #pragma unroll
            for (int d = 0; d < D_DIM; d++)
                a += __ldg(emb + tid * D_DIM + d) * __ldg(W + h * WSTR + 1 + d);
            r[h] = a;
        }
        g_embT[tid] = make_float4(r[0], r[1], r[2], r[3]);
    }
}

// ---------------------------------------------------------------------------
// K2: resolve all edges inline. cnt==1 → singleton. cnt>=2 → telescoping
// delta via exact hash: add ex(c_new)-ex(c_old); sums to exact group value
// in any arrival order (ex(0)=0). No later pass needed.
// ---------------------------------------------------------------------------
__device__ __forceinline__ void group_ex(
        unsigned int c, float si, float sj,
        float ws, float wt, float et0, float et1, float et2, float et3,
        float* exv) {
    // counts packed per type; a = (si*ws+sj*wt)*ctot + sum_t c_t*embT[t]
    float c0 = (float)( c        & 0xFFu);
    float c1 = (float)((c >> 8 ) & 0xFFu);
    float c2 = (float)((c >> 16) & 0xFFu);
    float c3 = (float)((c >> 24) & 0xFFu);
    float a = (si * ws + sj * wt) * (c0 + c1 + c2 + c3)
            + c0 * et0 + c1 * et1 + c2 * et2 + c3 * et3;
    *exv = __expf(fmaxf(a, NEG_SLOPE * a)) - 1.f;
}

__global__ void __launch_bounds__(256) k_edges(
        const int*   __restrict__ ei,
        const float* __restrict__ scores,
        const float* __restrict__ W) {
    const int gtid = blockIdx.x * 256 + threadIdx.x;
    const int base = gtid * 4;
    const int t = base >> 17, e = base & (E_EDGES - 1);

    int4 s4 = __ldg((const int4*)(ei + (t * 2    ) * E_EDGES + e));
    int4 t4 = __ldg((const int4*)(ei + (t * 2 + 1) * E_EDGES + e));

    unsigned int key[4], f[4], w[4];
    key[0] = ((unsigned)s4.x << 13) | (unsigned)t4.x;  f[0] = field_of(key[0]);
    key[1] = ((unsigned)s4.y << 13) | (unsigned)t4.y;  f[1] = field_of(key[1]);
    key[2] = ((unsigned)s4.z << 13) | (unsigned)t4.z;  f[2] = field_of(key[2]);
    key[3] = ((unsigned)s4.w << 13) | (unsigned)t4.w;  f[3] = field_of(key[3]);
    #pragma unroll
    for (int k = 0; k < 4; k++)
        w[k] = __ldg(&g_lsy[f[k] >> 3]);   // read-only in this kernel → safe

    float4 embT = *(const float4*)&g_embT[t];   // written in K1 (prev kernel)
    float ws0 = __ldg(W + 0 * WSTR), wt0 = __ldg(W + 0 * WSTR + 33);
    float ws1 = __ldg(W + 1 * WSTR), wt1 = __ldg(W + 1 * WSTR + 33);
    float ws2 = __ldg(W + 2 * WSTR), wt2 = __ldg(W + 2 * WSTR + 33);
    float ws3 = __ldg(W + 3 * WSTR), wt3 = __ldg(W + 3 * WSTR + 33);

    #pragma unroll
    for (int k = 0; k < 4; k++) {
        unsigned int cnt = (w[k] >> ((f[k] & 7u) * 4u)) & 15u;
        unsigned int src = key[k] >> 13, tgt = key[k] & 8191u;
        float si = __ldg(scores + src);
        float sj = __ldg(scores + tgt);
        float ex0, ex1, ex2, ex3;

        if (cnt == 1u) {                    // exact singleton (~94%)
            float a0 = si * ws0 + sj * wt0 + embT.x;
            float a1 = si * ws1 + sj * wt1 + embT.y;
            float a2 = si * ws2 + sj * wt2 + embT.z;
            float a3 = si * ws3 + sj * wt3 + embT.w;
            ex0 = __expf(fmaxf(a0, NEG_SLOPE * a0)) - 1.f;
            ex1 = __expf(fmaxf(a1, NEG_SLOPE * a1)) - 1.f;
            ex2 = __expf(fmaxf(a2, NEG_SLOPE * a2)) - 1.f;
            ex3 = __expf(fmaxf(a3, NEG_SLOPE * a3)) - 1.f;
        } else {                            // dup/collision: telescoping delta
            unsigned int hh = key[k] * 0x85EBCA6Bu;
            hh = (hh ^ (hh >> 16)) & DUP_MASK;
            while (true) {
                unsigned int o = atomicCAS(&g_dkey[hh], 0u, key[k] + 1u);
                if (o == 0u || o == key[k] + 1u) break;
                hh = (hh + 1u) & DUP_MASK;
            }
            unsigned int inc   = 1u << (t * 8);
            unsigned int c_old = atomicAdd(&g_dcnt[hh], inc);
            unsigned int c_new = c_old + inc;
            // per-head group values at old and new counts; delta telescopes
            float eo, en;
            float4 E0 = g_embT[0], E1 = g_embT[1], E2 = g_embT[2], E3 = g_embT[3];
            group_ex(c_new, si, sj, ws0, wt0, E0.x, E1.x, E2.x, E3.x, &en);
            group_ex(c_old, si, sj, ws0, wt0, E0.x, E1.x, E2.x, E3.x, &eo);
            ex0 = en - eo;
            group_ex(c_new, si, sj, ws1, wt1, E0.y, E1.y, E2.y, E3.y, &en);
            group_ex(c_old, si, sj, ws1, wt1, E0.y, E1.y, E2.y, E3.y, &eo);
            ex1 = en - eo;
            group_ex(c_new, si, sj, ws2, wt2, E0.z, E1.z, E2.z, E3.z, &en);
            group_ex(c_old, si, sj, ws2, wt2, E0.z, E1.z, E2.z, E3.z, &eo);
            ex2 = en - eo;
            group_ex(c_new, si, sj, ws3, wt3, E0.w, E1.w, E2.w, E3.w, &en);
            group_ex(c_old, si, sj, ws3, wt3, E0.w, E1.w, E2.w, E3.w, &eo);
            ex3 = en - eo;
        }

        float4* dst = &g_acc[src * 2];
        asm volatile("red.global.add.v4.f32 [%0], {%1,%2,%3,%4};"
                     :: "l"(dst), "f"(ex0), "f"(ex0 * sj),
                        "f"(ex1), "f"(ex1 * sj) : "memory");
        asm volatile("red.global.add.v4.f32 [%0], {%1,%2,%3,%4};"
                     :: "l"(dst + 1), "f"(ex2), "f"(ex2 * sj),
                        "f"(ex3), "f"(ex3 * sj) : "memory");
    }
}

// ---------------------------------------------------------------------------
// K3: blocks [0,32) finalize + reset g_acc; [32,96) clear lossy table;
//     [96,128) clear dup hash. No internal ordering required.
// ---------------------------------------------------------------------------
__global__ void __launch_bounds__(256) k_final(float* __restrict__ out) {
    const int bid = blockIdx.x, tid = threadIdx.x;
    uint4 z4 = make_uint4(0u, 0u, 0u, 0u);

    if (bid < FIN_BLOCKS) {
        float st = 0.f;
        #pragma unroll
        for (int k = 0; k < 32; k++) st += g_part[k];   // deterministic order
        int i = bid * 256 + tid;
        float4 a0 = g_acc[i * 2];
        float4 a1 = g_acc[i * 2 + 1];
        out[i] = 0.25f * ((st + a0.y) / (8192.f + a0.x)
                        + (st + a0.w) / (8192.f + a0.z)
                        + (st + a1.y) / (8192.f + a1.x)
                        + (st + a1.w) / (8192.f + a1.z));
        g_acc[i * 2]     = make_float4(0.f, 0.f, 0.f, 0.f);
        g_acc[i * 2 + 1] = make_float4(0.f, 0.f, 0.f, 0.f);
    } else if (bid < FIN_BLOCKS + CLR_L_BLOCKS) {
        uint4* l4 = (uint4*)g_lsy;                       // 2^18 uint4
        unsigned int b = (unsigned)(bid - FIN_BLOCKS) * 256 + tid;
        #pragma unroll
        for (int k = 0; k < 16; k++)
            l4[b + k * (CLR_L_BLOCKS * 256)] = z4;
    } else {
        uint4* k4 = (uint4*)g_dkey;                      // 2^15 uint4
        uint4* c4 = (uint4*)g_dcnt;
        unsigned int b = (unsigned)(bid - FIN_BLOCKS - CLR_L_BLOCKS) * 256 + tid;
        #pragma unroll
        for (int k = 0; k < 4; k++) {
            k4[b + k * (CLR_D_BLOCKS * 256)] = z4;
            c4[b + k * (CLR_D_BLOCKS * 256)] = z4;
        }
    }
}

// ---------------------------------------------------------------------------
extern "C" void kernel_launch(void* const* d_in, const int* in_sizes, int n_in,
                              void* d_out, int out_size) {
    const float* scores = (const float*)d_in[0];   // (N, 1)
    const float* emb    = (const float*)d_in[1];   // (T, D)
    const int*   ei     = (const int*)  d_in[2];   // (T, 2, E)
    const float* W      = (const float*)d_in[3];   // (H, D+2, 1)
    float*       out    = (float*)d_out;           // (N, 1)

    k_count<<<EDGE_BLOCKS, 256>>>(ei, scores, emb, W);
    k_edges<<<EDGE_BLOCKS, 256>>>(ei, scores, W);
    k_final<<<K3_BLOCKS,   256>>>(out);
}